// round 16
// baseline (speedup 1.0000x reference)
#include <cuda_runtime.h>
#include <cstdint>
#include <cstddef>

// Problem shape (fixed by the reference setup_inputs)
#define BB 64
#define TT 2048
#define NN 32
#define KCH 8            // steps per super-step (chunk)
#define XCH 3            // transposed-tile ring chunks
#define NTH 256
#define KNINF (-1e4f)
#define NEG_BIG (-3.402823466e38f)
#define LSEG 128
#define MAXSEG (TT / LSEG)   // 16

// Transposed tile layout (per 4KB tile): column j at floats [j*32, j*32+32);
// 16B chunk c (i = 4c..4c+3) stored rotated at float offset ((c+j)&7)*4.

struct __align__(16) Smem {
    float x[XCH][KCH * NN * NN];      // 96KB folded (phi+tr), transposed tiles
    float rawT[2][3][2 * NN * NN];    // 48KB raw rings: [Twarp][slot][2 tiles]
    float aring[32][NN];              // 4KB alpha ring, slot = t & 31
    unsigned char back[TT][NN];       // 64KB backpointers
    unsigned char M[MAXSEG][NN];      // composed segment maps
    int entry[MAXSEG];
    int misc[16];                     // [0..7] warp counts, [8] last_tag
};

__device__ __forceinline__ void cp16(unsigned dst, const void* src) {
    asm volatile("cp.async.cg.shared.global [%0], [%1], 16;" :: "r"(dst), "l"(src));
}
__device__ __forceinline__ void cp_commit() { asm volatile("cp.async.commit_group;"); }
template<int Nn> __device__ __forceinline__ void cp_wait() {
    asm volatile("cp.async.wait_group %0;" :: "n"(Nn));
}

__global__ void __launch_bounds__(NTH, 1)
viterbi_kernel(const float* __restrict__ lp, const int* __restrict__ mask,
               const int* __restrict__ startc, const int* __restrict__ endc,
               const int* __restrict__ transc, float* __restrict__ out)
{
    extern __shared__ __align__(16) char smraw[];
    Smem& sm = *reinterpret_cast<Smem*>(smraw);
    const int b    = blockIdx.x;
    const int tid  = threadIdx.x;
    const int w    = tid >> 5;
    const int lane = tid & 31;

    // ---- sequence length (mask is prefix-true) ----
    int cnt = 0;
    #pragma unroll
    for (int t = tid; t < TT; t += NTH) cnt += (mask[b * TT + t] != 0);
    #pragma unroll
    for (int o = 16; o; o >>= 1) cnt += __shfl_xor_sync(0xffffffffu, cnt, o);
    if (lane == 0) sm.misc[w] = cnt;
    __syncthreads();
    int len = 0;
    #pragma unroll
    for (int q = 0; q < 8; q++) len += sm.misc[q];
    const int last = len - 1;

    const float* lpb = lp + (size_t)b * TT * NN * NN;
    const int SSMAX = last / KCH + 2;

    if (w == 0) {
        // ================= alpha warp (SMSP0, solo): lane = column j =================
        const int j = lane;
        const float sp_j = startc[j] ? 0.0f : KNINF;
        const float ep_j = endc[j]   ? 0.0f : KNINF;

        // t = 0 from gmem: alpha0 = max_i phi0[i][j] + sp (+ep if len==1)
        float bv = NEG_BIG;
        #pragma unroll
        for (int i = 0; i < NN; i++) bv = fmaxf(bv, __ldg(lpb + i * NN + j));
        sm.aring[0][j] = (bv + sp_j) + ((last == 0) ? ep_j : 0.0f);

        for (int ss = 0; ss < SSMAX; ss++) {
            __syncthreads();                    // x chunk ss ready
            int tlo = (ss == 0) ? 1 : (KCH * ss);
            int thi = min(last, KCH * ss + KCH - 1);
            if (tlo > thi) continue;
            const float* xch = sm.x[ss % XCH];
            const bool haveEnd = (thi == last);
            const int thiN = haveEnd ? thi - 1 : thi;

            for (int t = tlo; t <= thiN; t++) {   // normal steps: s = (phi+tr) + a
                const float* tcol = xch + ((t & 7) << 10) + (j << 5);
                const float* ar = sm.aring[(t - 1) & 31];
                float s[NN];
                #pragma unroll
                for (int c = 0; c < 8; c++) {
                    float4 tv = *reinterpret_cast<const float4*>(tcol + (((c + j) & 7) << 2));
                    float4 av = *reinterpret_cast<const float4*>(ar + (c << 2));
                    s[4*c+0] = tv.x + av.x;  s[4*c+1] = tv.y + av.y;
                    s[4*c+2] = tv.z + av.z;  s[4*c+3] = tv.w + av.w;
                }
                #pragma unroll
                for (int off = 1; off < NN; off <<= 1)
                    #pragma unroll
                    for (int i = 0; i < NN; i += 2 * off)
                        s[i] = fmaxf(s[i], s[i + off]);
                sm.aring[t & 31][j] = s[0];
                __syncwarp();
            }
            if (haveEnd) {                       // peeled end step: ((phi+tr)+ep)+a
                const int t = last;
                const float* tcol = xch + ((t & 7) << 10) + (j << 5);
                const float* ar = sm.aring[(t - 1) & 31];
                float s[NN];
                #pragma unroll
                for (int c = 0; c < 8; c++) {
                    float4 tv = *reinterpret_cast<const float4*>(tcol + (((c + j) & 7) << 2));
                    float4 av = *reinterpret_cast<const float4*>(ar + (c << 2));
                    s[4*c+0] = (tv.x + ep_j) + av.x;  s[4*c+1] = (tv.y + ep_j) + av.y;
                    s[4*c+2] = (tv.z + ep_j) + av.z;  s[4*c+3] = (tv.w + ep_j) + av.w;
                }
                #pragma unroll
                for (int off = 1; off < NN; off <<= 1)
                    #pragma unroll
                    for (int i = 0; i < NN; i += 2 * off)
                        s[i] = fmaxf(s[i], s[i + off]);
                sm.aring[t & 31][j] = s[0];
                __syncwarp();
            }
        }
    } else if (w == 1 || w == 2) {
        // ===== transpose+fold producers (SMSP1/SMSP2). w1: tiles %8 0..3; w2: 4..7 =====
        const int j = lane;
        const int woff = w - 1;
        const int tileOff = woff * 4;
        float trv[NN];
        #pragma unroll
        for (int i = 0; i < NN; i++)
            trv[i] = transc[i * NN + j] ? 0.0f : KNINF;
        const unsigned rawBase = (unsigned)__cvta_generic_to_shared(&sm.rawT[0][0][0])
                                 + (unsigned)(woff * 24576);

        auto issue = [&](int g) {               // 2-tile group g -> raw slot g%3
            #pragma unroll
            for (int r = 0; r < 16; r++) {
                int cid = lane + 32 * r;
                int u = cid >> 8, within = cid & 255;
                int ri = within >> 3, c = within & 7;
                int t_g = 8 * (g >> 1) + 2 * (g & 1) + u + tileOff;
                if (t_g <= last) {
                    unsigned dst = rawBase + (unsigned)((g % 3) * 8192 + u * 4096
                                   + ri * 128 + ((c * 16) ^ ((ri & 16) ? 64 : 0)));
                    cp16(dst, lpb + (size_t)t_g * (NN * NN) + ri * NN + c * 4);
                }
            }
            cp_commit();
        };
        auto xpose = [&](int g) {               // fold tr, write transposed
            #pragma unroll
            for (int u = 0; u < 2; u++) {
                int t_g = 8 * (g >> 1) + 2 * (g & 1) + u + tileOff;
                if (t_g >= 1 && t_g <= last) {
                    const float* rw = sm.rawT[woff][g % 3] + u * (NN * NN);
                    float tv[NN];
                    #pragma unroll
                    for (int i = 0; i < NN; i++)
                        tv[i] = rw[i * NN + (j ^ (i & 16))] + trv[i];
                    float* dc = sm.x[(t_g >> 3) % XCH] + ((t_g & 7) << 10) + (j << 5);
                    #pragma unroll
                    for (int c = 0; c < 8; c++)
                        *reinterpret_cast<float4*>(dc + (((c + j) & 7) << 2)) =
                            make_float4(tv[4*c], tv[4*c+1], tv[4*c+2], tv[4*c+3]);
                }
            }
        };

        issue(0); issue(1); issue(2);
        cp_wait<2>(); __syncwarp(); xpose(0);
        issue(3);
        cp_wait<2>(); __syncwarp(); xpose(1);
        __syncwarp();
        for (int ss = 0; ss < SSMAX; ss++) {
            __syncthreads();
            issue(2 * ss + 4);
            cp_wait<2>(); __syncwarp(); xpose(2 * ss + 2);   // chunk ss+1, 1st half
            __syncwarp();
            issue(2 * ss + 5);
            cp_wait<2>(); __syncwarp(); xpose(2 * ss + 3);   // chunk ss+1, 2nd half
            __syncwarp();
        }
        cp_wait<0>();
    } else if (w == 5 || w == 6 || w == 3 || w == 7) {
        // ===== backpointer warps: 8 columns each, 4 lanes/col, 8 i's/lane =====
        // Placement by SMSP: w5->SMSP1, w6->SMSP2, w3+w7->SMSP3 (each ~50 inst/step)
        const int bpIdx = (w == 5) ? 0 : (w == 6) ? 1 : (w == 3) ? 2 : 3;
        const int j = bpIdx * 8 + (lane >> 2);
        const int q = lane & 3;                 // i in [8q, 8q+8)
        const float ep_j = endc[j] ? 0.0f : KNINF;
        const unsigned colmask4 = 0xFu << (lane & ~3);

        for (int ss = 0; ss < SSMAX; ss++) {
            __syncthreads();
            if (ss < 1) continue;
            int tlo = max(1, (ss - 1) * KCH);
            int thi = min(last, (ss - 1) * KCH + KCH - 1);
            if (tlo > thi) continue;
            const float* xch = sm.x[(ss - 1) % XCH];
            for (int t = tlo; t <= thi; t++) {
                const float* tcol = xch + ((t & 7) << 10) + (j << 5);
                const float* ar = sm.aring[(t - 1) & 31] + q * 8;
                float4 a0 = reinterpret_cast<const float4*>(ar)[0];
                float4 a1 = reinterpret_cast<const float4*>(ar)[1];
                const int c0 = 2 * q, c1 = 2 * q + 1;
                float4 t0 = *reinterpret_cast<const float4*>(tcol + (((c0 + j) & 7) << 2));
                float4 t1 = *reinterpret_cast<const float4*>(tcol + (((c1 + j) & 7) << 2));
                float sv[8];
                if (t != last) {
                    sv[0] = t0.x + a0.x; sv[1] = t0.y + a0.y;
                    sv[2] = t0.z + a0.z; sv[3] = t0.w + a0.w;
                    sv[4] = t1.x + a1.x; sv[5] = t1.y + a1.y;
                    sv[6] = t1.z + a1.z; sv[7] = t1.w + a1.w;
                } else {
                    sv[0] = (t0.x + ep_j) + a0.x; sv[1] = (t0.y + ep_j) + a0.y;
                    sv[2] = (t0.z + ep_j) + a0.z; sv[3] = (t0.w + ep_j) + a0.w;
                    sv[4] = (t1.x + ep_j) + a1.x; sv[5] = (t1.y + ep_j) + a1.y;
                    sv[6] = (t1.z + ep_j) + a1.z; sv[7] = (t1.w + ep_j) + a1.w;
                }
                float m[8];
                #pragma unroll
                for (int k = 0; k < 8; k++) m[k] = sv[k];
                #pragma unroll
                for (int off = 1; off < 8; off <<= 1)
                    #pragma unroll
                    for (int k = 0; k < 8; k += 2 * off)
                        m[k] = fmaxf(m[k], m[k + off]);
                const float lm = m[0];
                int idx = 7;
                #pragma unroll
                for (int k = 6; k >= 0; k--)
                    if (sv[k] == lm) idx = k;             // first-max within 8
                const int gi = q * 8 + idx;
                // column max over the 4 lanes (value only)
                float bf = fmaxf(lm, __shfl_xor_sync(0xffffffffu, lm, 1));
                bf = fmaxf(bf, __shfl_xor_sync(0xffffffffu, bf, 2));
                unsigned ball = __ballot_sync(0xffffffffu, lm == bf);
                int src = __ffs(ball & colmask4) - 1;     // lowest q = smallest i
                int bif = __shfl_sync(0xffffffffu, gi, src);
                if (q == 0) sm.back[t][j] = (unsigned char)bif;
            }
        }
    } else {
        // idle warp (w4): barrier keeper
        for (int ss = 0; ss < SSMAX; ss++) __syncthreads();
    }

    __syncthreads();   // alpha[last], back[] all published

    // ---- final max / argmax over tags (first occurrence) ----
    if (w == 0) {
        float v  = sm.aring[last & 31][lane];
        int  idx = lane;
        #pragma unroll
        for (int o = 16; o; o >>= 1) {
            float ov = __shfl_xor_sync(0xffffffffu, v, o);
            int   oi = __shfl_xor_sync(0xffffffffu, idx, o);
            if (ov > v || (ov == v && oi < idx)) { v = ov; idx = oi; }
        }
        if (lane == 0) { out[b] = v; sm.misc[8] = idx; }
    }
    __syncthreads();
    const int last_tag = sm.misc[8];

    float* tags = out + BB + (size_t)b * TT;
    for (int t = len + tid; t < TT; t += NTH) tags[t] = -1.0f;   // PADDING_INDEX

    if (last == 0) {
        if (tid == 0) tags[0] = (float)last_tag;
        return;
    }

    // ---- parallel backtrack: segment-composed pointer chase ----
    const int nseg = (last + LSEG - 1) / LSEG;
    for (int q = tid; q < nseg * NN; q += NTH) {
        const int s  = q >> 5;
        int y        = q & 31;
        const int lo = s * LSEG;
        const int hi = min((s + 1) * LSEG, last);
        for (int t = hi; t > lo; t--) y = sm.back[t][y];
        sm.M[s][q & 31] = (unsigned char)y;
    }
    __syncthreads();
    if (tid == 0) {
        int cur = last_tag;
        sm.entry[nseg - 1] = cur;
        for (int s = nseg - 1; s >= 1; s--) {
            cur = sm.M[s][cur];
            sm.entry[s - 1] = cur;
        }
        tags[0] = (float)sm.M[0][cur];
    }
    __syncthreads();
    if (tid < nseg) {
        const int s  = tid;
        const int lo = s * LSEG;
        const int hi = min((s + 1) * LSEG, last);
        int cur = sm.entry[s];
        for (int t = hi; t > lo; t--) {
            tags[t] = (float)cur;
            cur = sm.back[t][cur];
        }
    }
}

extern "C" void kernel_launch(void* const* d_in, const int* in_sizes, int n_in,
                              void* d_out, int out_size)
{
    const float* lp   = (const float*)d_in[0];
    const int* mask   = (const int*)d_in[1];
    const int* startc = (const int*)d_in[2];
    const int* endc   = (const int*)d_in[3];
    const int* transc = (const int*)d_in[4];
    float* out = (float*)d_out;
    (void)in_sizes; (void)n_in; (void)out_size;

    const int smem_bytes = (int)sizeof(Smem);   // ~213 KB (< 227 KB limit)
    cudaFuncSetAttribute(viterbi_kernel,
                         cudaFuncAttributeMaxDynamicSharedMemorySize, smem_bytes);
    viterbi_kernel<<<BB, NTH, smem_bytes>>>(lp, mask, startc, endc, transc, out);
}

// round 17
// speedup vs baseline: 1.0401x; 1.0401x over previous
#include <cuda_runtime.h>
#include <cstdint>
#include <cstddef>

// Problem shape (fixed by the reference setup_inputs)
#define BB 64
#define TT 2048
#define NN 32
#define DD 8            // cp.async ring stages (R3-proven wait pattern)
#define NTH 64          // 2 warps: minimum barrier participants
#define KNINF (-1e4f)
#define NEG_BIG (-3.402823466e38f)
#define LSEG 128
#define MAXSEG (TT / LSEG)   // 16

struct __align__(16) Smem {
    float tiles[DD][NN * NN];        // 32 KB, swizzled rows (R3 layout)
    float alpha[2][NN];              // double-buffered alpha
    unsigned char back[TT][NN];      // 64 KB backpointers
    unsigned char M[MAXSEG][NN];     // composed segment maps
    int entry[MAXSEG];               // tag at hi of each segment
    int misc[8];                     // [0..1] warp counts, [5] last_tag
};

__device__ __forceinline__ void cp16(unsigned dst, const void* src) {
    asm volatile("cp.async.cg.shared.global [%0], [%1], 16;" :: "r"(dst), "l"(src));
}
__device__ __forceinline__ void cp_commit() { asm volatile("cp.async.commit_group;"); }
template<int Nn> __device__ __forceinline__ void cp_wait() {
    asm volatile("cp.async.wait_group %0;" :: "n"(Nn));
}

__global__ void __launch_bounds__(NTH, 1)
viterbi_kernel(const float* __restrict__ lp, const int* __restrict__ mask,
               const int* __restrict__ startc, const int* __restrict__ endc,
               const int* __restrict__ transc, float* __restrict__ out)
{
    extern __shared__ __align__(16) char smraw[];
    Smem& sm = *reinterpret_cast<Smem*>(smraw);
    const int b    = blockIdx.x;
    const int tid  = threadIdx.x;
    const int w    = tid >> 5;        // warp id: owns columns j = 16w..16w+15
    const int lane = tid & 31;
    const int jloc = lane & 15;
    const int h    = lane >> 4;       // i-half: i = 16h .. 16h+15
    const int j    = w * 16 + jloc;
    const int i0   = h * 16;
    const unsigned colmask = 0x00010001u << jloc;   // the 2 lanes of column j

    // ---- sequence length (mask is prefix-true) ----
    int cnt = 0;
    #pragma unroll
    for (int t = tid; t < TT; t += NTH) cnt += (mask[b * TT + t] != 0);
    #pragma unroll
    for (int o = 16; o; o >>= 1) cnt += __shfl_xor_sync(0xffffffffu, cnt, o);
    if (lane == 0) sm.misc[w] = cnt;
    __syncthreads();
    const int len  = sm.misc[0] + sm.misc[1];
    const int last = len - 1;

    // ---- per-thread constants ----
    float tr[16];
    #pragma unroll
    for (int k = 0; k < 16; k++)
        tr[k] = transc[(i0 + k) * NN + j] ? 0.0f : KNINF;
    const float sp_j = startc[j] ? 0.0f : KNINF;
    const float ep_j = endc[j]   ? 0.0f : KNINF;

    const float* lpb = lp + (size_t)b * TT * NN * NN;

    // ---- cp.async slice: each thread copies four 16B chunks per tile ----
    // Swizzle (R3): 16B-chunk cc of row r stored at byte r*128 + ((16*cc + 32*(r>>3)) & 127)
    const int c4   = tid * 4;
    const int rowA = c4 >> 3;          // chunks c4..c4+3 span rows rowA (maybe rowA+?)
    // chunks c4+0..3: cc = (c4&7)..(c4&7)+3, all within row rowA since c4 % 8 == {0,4}
    const int ccA  = c4 & 7;
    const unsigned swzA = (unsigned)((rowA >> 3) << 5);
    unsigned dOff[4];
    #pragma unroll
    for (int e = 0; e < 4; e++)
        dOff[e] = (unsigned)(rowA * 128) + (((unsigned)((ccA + e) * 16) + swzA) & 127u);
    const float* srcBase = lpb + rowA * NN + ccA * 4;
    const unsigned tilesBase = (unsigned)__cvta_generic_to_shared(&sm.tiles[0][0]);
    // reader: element (i, j) lives at tiles[stage][ i*32 + ((j + 8*(i>>3)) & 31) ]
    const int cOffLo = (j + 8 * (2 * h))     & 31;   // rows i0..i0+7
    const int cOffHi = (j + 8 * (2 * h + 1)) & 31;   // rows i0+8..i0+15

    // ---- prologue: issue tiles 0..DD-2 (one commit group per tile slot) ----
    for (int k = 0; k < DD - 1; k++) {
        if (k <= last) {
            unsigned sb = tilesBase + (unsigned)(k * (NN * NN * 4));
            const float* s0 = srcBase + (size_t)k * NN * NN;
            #pragma unroll
            for (int e = 0; e < 4; e++) cp16(sb + dOff[e], s0 + 4 * e);
        }
        cp_commit();
    }

    // ---- t = 0: alpha0[j] = max_i lp[0,i,j] + start_pen (+ end_pen if len==1) ----
    cp_wait<DD - 2>();
    __syncthreads();
    {
        const int ft = DD - 1;
        if (ft <= last) {
            unsigned sb = tilesBase + (unsigned)((ft % DD) * (NN * NN * 4));
            const float* s0 = srcBase + (size_t)ft * NN * NN;
            #pragma unroll
            for (int e = 0; e < 4; e++) cp16(sb + dOff[e], s0 + 4 * e);
        }
        cp_commit();

        const float* tile = sm.tiles[0];
        float best = NEG_BIG;
        #pragma unroll
        for (int k = 0; k < 8; k++)
            best = fmaxf(best, tile[(i0 + k) * NN + cOffLo]);
        #pragma unroll
        for (int k = 8; k < 16; k++)
            best = fmaxf(best, tile[(i0 + k) * NN + cOffHi]);
        best = fmaxf(best, __shfl_xor_sync(0xffffffffu, best, 16));
        if (h == 0) {
            float e = (last == 0) ? ep_j : 0.0f;
            sm.alpha[0][j] = (best + sp_j) + e;   // const-in-i shift commutes with max
        }
    }

    // ---- main forward loop: ONE __syncthreads per step (R3-proven structure) ----
    int p = 0;                 // alpha[p] holds alpha_{t-1}
    float ps[16];              // previous step's 16 sums (for deferred argmax)
    float plocal = 0.0f;       // previous lane-local max
    float pbestf = 0.0f;       // previous column-final max

    for (int t = 1; t <= last; t++) {
        cp_wait<DD - 2>();
        __syncthreads();   // tile t visible; alpha(t-1) visible; stage (t-1)%DD free

        const int ft = t + DD - 1;
        if (ft <= last) {
            unsigned sb = tilesBase + (unsigned)((ft % DD) * (NN * NN * 4));
            const float* s0 = srcBase + (size_t)ft * NN * NN;
            #pragma unroll
            for (int e = 0; e < 4; e++) cp16(sb + dOff[e], s0 + 4 * e);
        }
        cp_commit();

        // issue tile + alpha loads first (LDS shadow follows)
        const float* tile = sm.tiles[t % DD];
        float tv[16];
        #pragma unroll
        for (int k = 0; k < 8; k++)  tv[k] = tile[(i0 + k) * NN + cOffLo];
        #pragma unroll
        for (int k = 8; k < 16; k++) tv[k] = tile[(i0 + k) * NN + cOffHi];
        float a[16];
        #pragma unroll
        for (int q = 0; q < 4; q++) {
            float4 v = reinterpret_cast<const float4*>(&sm.alpha[p][i0])[q];
            a[4*q] = v.x; a[4*q+1] = v.y; a[4*q+2] = v.z; a[4*q+3] = v.w;
        }

        // ---- deferred backpointer for step t-1 (fills the load shadow) ----
        if (t > 1) {
            int bi = 15;
            #pragma unroll
            for (int k = 14; k >= 0; k--) if (ps[k] == plocal) bi = k;  // first-max in k
            bi += i0;
            unsigned ball = __ballot_sync(0xffffffffu, plocal == pbestf);
            int src = __ffs(ball & colmask) - 1;      // h=0 lane first = smaller i
            int bif = __shfl_sync(0xffffffffu, bi, src);
            if (h == 0) sm.back[t - 1][j] = (unsigned char)bif;
        }

        // ---- value-only alpha update (exact FP order preserved from ref) ----
        float s[16];
        if (t != last) {
            #pragma unroll
            for (int k = 0; k < 16; k++) s[k] = (tv[k] + tr[k]) + a[k];
        } else {   // peeled end step: ((phi+tr)+ep)+alpha
            #pragma unroll
            for (int k = 0; k < 16; k++) s[k] = ((tv[k] + tr[k]) + ep_j) + a[k];
        }
        #pragma unroll
        for (int k = 0; k < 16; k++) ps[k] = s[k];
        float m[16];
        #pragma unroll
        for (int k = 0; k < 16; k++) m[k] = s[k];
        #pragma unroll
        for (int off = 1; off < 16; off <<= 1)
            #pragma unroll
            for (int k = 0; k < 16; k += 2 * off)
                m[k] = fmaxf(m[k], m[k + off]);
        const float local = m[0];
        float bf = fmaxf(local, __shfl_xor_sync(0xffffffffu, local, 16));
        if (h == 0) sm.alpha[p ^ 1][j] = bf;

        plocal = local; pbestf = bf;
        p ^= 1;
    }

    // flush last step's backpointer
    if (last >= 1) {
        int bi = 15;
        #pragma unroll
        for (int k = 14; k >= 0; k--) if (ps[k] == plocal) bi = k;
        bi += i0;
        unsigned ball = __ballot_sync(0xffffffffu, plocal == pbestf);
        int src = __ffs(ball & colmask) - 1;
        int bif = __shfl_sync(0xffffffffu, bi, src);
        if (h == 0) sm.back[last][j] = (unsigned char)bif;
    }

    cp_wait<0>();
    __syncthreads();

    // ---- final max / argmax over tags (first occurrence) ----
    if (w == 0) {
        float v  = sm.alpha[p][lane];
        int  idx = lane;
        #pragma unroll
        for (int o = 16; o; o >>= 1) {
            float ov = __shfl_xor_sync(0xffffffffu, v, o);
            int   oi = __shfl_xor_sync(0xffffffffu, idx, o);
            if (ov > v || (ov == v && oi < idx)) { v = ov; idx = oi; }
        }
        if (lane == 0) { out[b] = v; sm.misc[5] = idx; }
    }
    __syncthreads();
    const int last_tag = sm.misc[5];

    float* tags = out + BB + (size_t)b * TT;
    for (int t = len + tid; t < TT; t += NTH) tags[t] = -1.0f;   // PADDING_INDEX

    if (last == 0) {
        if (tid == 0) tags[0] = (float)last_tag;
        return;
    }

    // ---- parallel backtrack: segment-composed pointer chase ----
    const int nseg = (last + LSEG - 1) / LSEG;
    for (int q = tid; q < nseg * NN; q += NTH) {
        const int s  = q >> 5;
        int y        = q & 31;
        const int lo = s * LSEG;
        const int hi = min((s + 1) * LSEG, last);
        for (int t = hi; t > lo; t--) y = sm.back[t][y];
        sm.M[s][q & 31] = (unsigned char)y;   // tag at lo given tag(hi)=x
    }
    __syncthreads();
    if (tid == 0) {
        int cur = last_tag;                   // tag at hi of top segment (== last)
        sm.entry[nseg - 1] = cur;
        for (int s = nseg - 1; s >= 1; s--) {
            cur = sm.M[s][cur];               // tag at lo_s == hi_{s-1}
            sm.entry[s - 1] = cur;
        }
        tags[0] = (float)sm.M[0][cur];        // tag at position 0
    }
    __syncthreads();
    if (tid < nseg) {
        const int s  = tid;
        const int lo = s * LSEG;
        const int hi = min((s + 1) * LSEG, last);
        int cur = sm.entry[s];
        for (int t = hi; t > lo; t--) {
            tags[t] = (float)cur;
            cur = sm.back[t][cur];
        }
    }
}

extern "C" void kernel_launch(void* const* d_in, const int* in_sizes, int n_in,
                              void* d_out, int out_size)
{
    const float* lp   = (const float*)d_in[0];
    const int* mask   = (const int*)d_in[1];
    const int* startc = (const int*)d_in[2];
    const int* endc   = (const int*)d_in[3];
    const int* transc = (const int*)d_in[4];
    float* out = (float*)d_out;
    (void)in_sizes; (void)n_in; (void)out_size;

    const int smem_bytes = (int)sizeof(Smem);   // ~97 KB (< 227 KB limit)
    cudaFuncSetAttribute(viterbi_kernel,
                         cudaFuncAttributeMaxDynamicSharedMemorySize, smem_bytes);
    viterbi_kernel<<<BB, NTH, smem_bytes>>>(lp, mask, startc, endc, transc, out);
}